// round 1
// baseline (speedup 1.0000x reference)
#include <cuda_runtime.h>
#include <cstdint>
#include <math_constants.h>

#define B_ 4
#define S_ 2048
#define E_ 1024
#define H_ 16
#define D_ 64
#define M_ (B_*S_)

// ---------------- scratch (static device globals; no allocation) ----------------
__device__ float g_q[(size_t)B_*H_*S_*D_];
__device__ float g_k[(size_t)B_*H_*S_*D_];
__device__ float g_v[(size_t)B_*H_*S_*D_];
__device__ float g_attn[(size_t)M_*E_];
__device__ float g_y[(size_t)M_*E_];

// ---------------- helpers ----------------
__device__ __forceinline__ unsigned f2tf(float x){
    unsigned r; asm("cvt.rna.tf32.f32 %0, %1;" : "=r"(r) : "f"(x)); return r;
}
__device__ __forceinline__ float tf2f(float x){ return __uint_as_float(f2tf(x)); }
__device__ __forceinline__ unsigned fu(float x){ return __float_as_uint(x); }

__device__ __forceinline__ void mma8(float* c, const unsigned* a, const unsigned* b){
    asm volatile(
        "mma.sync.aligned.m16n8k8.row.col.f32.tf32.tf32.f32 "
        "{%0,%1,%2,%3},{%4,%5,%6,%7},{%8,%9},{%0,%1,%2,%3};"
        : "+f"(c[0]), "+f"(c[1]), "+f"(c[2]), "+f"(c[3])
        : "r"(a[0]), "r"(a[1]), "r"(a[2]), "r"(a[3]), "r"(b[0]), "r"(b[1]));
}

// ---------------- GEMM: C[M,N] = A[M,K] @ W[K,N] (+bias [+resid]) ----------------
// MODE 0/1/2: out = g_q/g_k/g_v scattered into [B,H,S,D]
// MODE 3:     A = g_attn, out = g_y = acc + bias + resid (row-major [M,E])
template<int MODE>
__global__ void __launch_bounds__(256)
gemm_kernel(const float* __restrict__ A, const float* __restrict__ W,
            const float* __restrict__ bias, const float* __restrict__ resid)
{
    __shared__ float As[128][20];   // [m][k], pad 20 -> conflict-free frag loads
    __shared__ float Bs[16][136];   // [k][n], pad 136 -> conflict-free frag loads

    const int tid = threadIdx.x, lane = tid & 31, wid = tid >> 5;
    const int gid = lane >> 2, t4 = lane & 3;
    const int wm = wid & 3, wn = wid >> 2;          // 4x2 warp grid; warp tile 32x64
    const int bm = blockIdx.y * 128, bn = blockIdx.x * 128;

    const float* Ap = (MODE == 3) ? g_attn : A;

    float acc[2][8][4] = {};

    const int ar = tid >> 2, ac = (tid & 3) * 4;    // A loads: 2 float4/thread
    const int bk = tid >> 5, bn4 = (tid & 31) * 4;  // W loads: 2 float4/thread

    for (int kt = 0; kt < E_; kt += 16) {
        #pragma unroll
        for (int i = 0; i < 2; i++) {
            float4 v = *reinterpret_cast<const float4*>(Ap + (size_t)(bm + ar + i*64)*E_ + kt + ac);
            As[ar + i*64][ac+0] = tf2f(v.x);
            As[ar + i*64][ac+1] = tf2f(v.y);
            As[ar + i*64][ac+2] = tf2f(v.z);
            As[ar + i*64][ac+3] = tf2f(v.w);
        }
        #pragma unroll
        for (int i = 0; i < 2; i++) {
            float4 v = *reinterpret_cast<const float4*>(W + (size_t)(kt + bk + i*8)*E_ + bn + bn4);
            Bs[bk + i*8][bn4+0] = tf2f(v.x);
            Bs[bk + i*8][bn4+1] = tf2f(v.y);
            Bs[bk + i*8][bn4+2] = tf2f(v.z);
            Bs[bk + i*8][bn4+3] = tf2f(v.w);
        }
        __syncthreads();

        #pragma unroll
        for (int ks = 0; ks < 16; ks += 8) {
            unsigned af[2][4];
            #pragma unroll
            for (int mi = 0; mi < 2; mi++) {
                int r = wm*32 + mi*16 + gid;
                af[mi][0] = fu(As[r    ][ks + t4    ]);
                af[mi][1] = fu(As[r + 8][ks + t4    ]);
                af[mi][2] = fu(As[r    ][ks + t4 + 4]);
                af[mi][3] = fu(As[r + 8][ks + t4 + 4]);
            }
            #pragma unroll
            for (int ni = 0; ni < 8; ni++) {
                unsigned bf[2];
                int n = wn*64 + ni*8 + gid;
                bf[0] = fu(Bs[ks + t4    ][n]);
                bf[1] = fu(Bs[ks + t4 + 4][n]);
                mma8(acc[0][ni], af[0], bf);
                mma8(acc[1][ni], af[1], bf);
            }
        }
        __syncthreads();
    }

    #pragma unroll
    for (int mi = 0; mi < 2; mi++)
    #pragma unroll
    for (int ni = 0; ni < 8; ni++)
    #pragma unroll
    for (int j = 0; j < 4; j++) {
        int row = bm + wm*32 + mi*16 + gid + ((j & 2) ? 8 : 0);
        int col = bn + wn*64 + ni*8 + t4*2 + (j & 1);
        float v = acc[mi][ni][j] + bias[col];
        if (MODE == 3) {
            g_y[(size_t)row*E_ + col] = v + resid[(size_t)row*E_ + col];
        } else {
            int b = row >> 11, s = row & (S_ - 1), h = col >> 6, d = col & 63;
            float* op = (MODE == 0) ? g_q : (MODE == 1) ? g_k : g_v;
            op[(((size_t)(b*H_ + h))*S_ + s)*D_ + d] = v;
        }
    }
}

// ---------------- flash attention: Br=Bc=64, 4 warps, online softmax ----------------
#define QS_STR 68
#define VS_STR 72
#define FLASH_SMEM ((3*64*QS_STR + 64*VS_STR) * (int)sizeof(float))

__global__ void __launch_bounds__(128)
flash_kernel()
{
    extern __shared__ float sm[];
    float* Qs = sm;                    // [64][68] (scaled, tf32)
    float* Ks = sm + 64*QS_STR;        // [64][68]
    float* Ps = sm + 2*64*QS_STR;      // [64][68]
    float* Vs = sm + 3*64*QS_STR;      // [64][72]

    const int tid = threadIdx.x, lane = tid & 31, w = tid >> 5;
    const int gid = lane >> 2, t4 = lane & 3;
    const int bh = blockIdx.y, q0 = blockIdx.x * 64;
    const float scale = 0.125f; // 1/sqrt(64)

    const float* qp = g_q + ((size_t)bh*S_ + q0)*D_;
    const float* kp = g_k + (size_t)bh*S_*D_;
    const float* vp = g_v + (size_t)bh*S_*D_;

    #pragma unroll
    for (int i = 0; i < 8; i++) {
        int e = tid + i*128; int r = e >> 4, c = (e & 15) * 4;
        float4 v = *reinterpret_cast<const float4*>(qp + (size_t)r*D_ + c);
        Qs[r*QS_STR + c + 0] = tf2f(v.x * scale);
        Qs[r*QS_STR + c + 1] = tf2f(v.y * scale);
        Qs[r*QS_STR + c + 2] = tf2f(v.z * scale);
        Qs[r*QS_STR + c + 3] = tf2f(v.w * scale);
    }

    float acc_o[8][4] = {};
    float m0 = -CUDART_INF_F, m1 = -CUDART_INF_F, l0 = 0.f, l1 = 0.f;
    const int r0 = w*16 + gid;

    for (int kv = 0; kv < S_; kv += 64) {
        __syncthreads();  // protect Ks/Vs from previous iteration's readers
        #pragma unroll
        for (int i = 0; i < 8; i++) {
            int e = tid + i*128; int r = e >> 4, c = (e & 15) * 4;
            float4 kvv = *reinterpret_cast<const float4*>(kp + ((size_t)(kv + r))*D_ + c);
            Ks[r*QS_STR + c + 0] = tf2f(kvv.x);
            Ks[r*QS_STR + c + 1] = tf2f(kvv.y);
            Ks[r*QS_STR + c + 2] = tf2f(kvv.z);
            Ks[r*QS_STR + c + 3] = tf2f(kvv.w);
            float4 vv = *reinterpret_cast<const float4*>(vp + ((size_t)(kv + r))*D_ + c);
            Vs[r*VS_STR + c + 0] = tf2f(vv.x);
            Vs[r*VS_STR + c + 1] = tf2f(vv.y);
            Vs[r*VS_STR + c + 2] = tf2f(vv.z);
            Vs[r*VS_STR + c + 3] = tf2f(vv.w);
        }
        __syncthreads();

        // S = Q @ K^T (warp w computes rows [16w,16w+16) x all 64 cols)
        float sc[8][4] = {};
        #pragma unroll
        for (int kk = 0; kk < 64; kk += 8) {
            unsigned a[4];
            a[0] = fu(Qs[r0*QS_STR     + kk + t4    ]);
            a[1] = fu(Qs[(r0+8)*QS_STR + kk + t4    ]);
            a[2] = fu(Qs[r0*QS_STR     + kk + t4 + 4]);
            a[3] = fu(Qs[(r0+8)*QS_STR + kk + t4 + 4]);
            #pragma unroll
            for (int ni = 0; ni < 8; ni++) {
                unsigned b[2]; int n = ni*8 + gid;
                b[0] = fu(Ks[n*QS_STR + kk + t4    ]);
                b[1] = fu(Ks[n*QS_STR + kk + t4 + 4]);
                mma8(sc[ni], a, b);
            }
        }

        // online softmax (rows r0 and r0+8; quad lanes t4=0..3 hold disjoint cols)
        float tm0 = -CUDART_INF_F, tm1 = -CUDART_INF_F;
        #pragma unroll
        for (int ni = 0; ni < 8; ni++) {
            tm0 = fmaxf(tm0, fmaxf(sc[ni][0], sc[ni][1]));
            tm1 = fmaxf(tm1, fmaxf(sc[ni][2], sc[ni][3]));
        }
        tm0 = fmaxf(tm0, __shfl_xor_sync(0xffffffffu, tm0, 1));
        tm0 = fmaxf(tm0, __shfl_xor_sync(0xffffffffu, tm0, 2));
        tm1 = fmaxf(tm1, __shfl_xor_sync(0xffffffffu, tm1, 1));
        tm1 = fmaxf(tm1, __shfl_xor_sync(0xffffffffu, tm1, 2));
        float mn0 = fmaxf(m0, tm0), mn1 = fmaxf(m1, tm1);
        float al0 = __expf(m0 - mn0), al1 = __expf(m1 - mn1);
        m0 = mn0; m1 = mn1;

        float ls0 = 0.f, ls1 = 0.f;
        #pragma unroll
        for (int ni = 0; ni < 8; ni++) {
            float p0 = __expf(sc[ni][0] - mn0);
            float p1 = __expf(sc[ni][1] - mn0);
            float p2 = __expf(sc[ni][2] - mn1);
            float p3 = __expf(sc[ni][3] - mn1);
            ls0 += p0 + p1; ls1 += p2 + p3;
            int cb = ni*8 + t4*2;
            Ps[r0*QS_STR     + cb    ] = tf2f(p0);
            Ps[r0*QS_STR     + cb + 1] = tf2f(p1);
            Ps[(r0+8)*QS_STR + cb    ] = tf2f(p2);
            Ps[(r0+8)*QS_STR + cb + 1] = tf2f(p3);
            acc_o[ni][0] *= al0; acc_o[ni][1] *= al0;
            acc_o[ni][2] *= al1; acc_o[ni][3] *= al1;
        }
        ls0 += __shfl_xor_sync(0xffffffffu, ls0, 1);
        ls0 += __shfl_xor_sync(0xffffffffu, ls0, 2);
        ls1 += __shfl_xor_sync(0xffffffffu, ls1, 1);
        ls1 += __shfl_xor_sync(0xffffffffu, ls1, 2);
        l0 = l0*al0 + ls0; l1 = l1*al1 + ls1;

        __syncwarp();  // Ps rows are warp-private; warp-level fence suffices

        // O += P @ V
        #pragma unroll
        for (int kk = 0; kk < 64; kk += 8) {
            unsigned a[4];
            a[0] = fu(Ps[r0*QS_STR     + kk + t4    ]);
            a[1] = fu(Ps[(r0+8)*QS_STR + kk + t4    ]);
            a[2] = fu(Ps[r0*QS_STR     + kk + t4 + 4]);
            a[3] = fu(Ps[(r0+8)*QS_STR + kk + t4 + 4]);
            #pragma unroll
            for (int ni = 0; ni < 8; ni++) {
                unsigned b[2]; int n = ni*8 + gid;
                b[0] = fu(Vs[(kk + t4    )*VS_STR + n]);
                b[1] = fu(Vs[(kk + t4 + 4)*VS_STR + n]);
                mma8(acc_o[ni], a, b);
            }
        }
    }

    float inv0 = 1.f / l0, inv1 = 1.f / l1;
    int b = bh >> 4, h = bh & 15;
    #pragma unroll
    for (int ni = 0; ni < 8; ni++)
    #pragma unroll
    for (int j = 0; j < 4; j++) {
        int r = r0 + ((j & 2) ? 8 : 0);
        int d = ni*8 + t4*2 + (j & 1);
        float v = acc_o[ni][j] * ((j & 2) ? inv1 : inv0);
        g_attn[((size_t)b*S_ + (q0 + r))*E_ + h*64 + d] = v;
    }
}

// ---------------- LayerNorm over g_y rows -> d_out ----------------
__global__ void __launch_bounds__(256)
ln_kernel(const float* __restrict__ gamma, const float* __restrict__ beta,
          float* __restrict__ out)
{
    __shared__ float red[8];
    const int row = blockIdx.x, tid = threadIdx.x;
    const int lane = tid & 31, wid = tid >> 5;
    const float* y = g_y + (size_t)row*E_;

    float4 v = *reinterpret_cast<const float4*>(y + tid*4);
    float s = v.x + v.y + v.z + v.w;
    #pragma unroll
    for (int o = 16; o > 0; o >>= 1) s += __shfl_xor_sync(0xffffffffu, s, o);
    if (lane == 0) red[wid] = s;
    __syncthreads();
    float tot = red[0];
    #pragma unroll
    for (int i = 1; i < 8; i++) tot += red[i];
    float mean = tot * (1.f / 1024.f);

    float d0 = v.x - mean, d1 = v.y - mean, d2 = v.z - mean, d3 = v.w - mean;
    float s2 = d0*d0 + d1*d1 + d2*d2 + d3*d3;
    #pragma unroll
    for (int o = 16; o > 0; o >>= 1) s2 += __shfl_xor_sync(0xffffffffu, s2, o);
    __syncthreads();  // all reads of red done before overwrite
    if (lane == 0) red[wid] = s2;
    __syncthreads();
    float tot2 = red[0];
    #pragma unroll
    for (int i = 1; i < 8; i++) tot2 += red[i];
    float rs = rsqrtf(tot2 * (1.f / 1024.f) + 1e-6f);

    const int c = tid * 4;
    float* op = out + (size_t)row*E_ + c;
    op[0] = d0 * rs * gamma[c + 0] + beta[c + 0];
    op[1] = d1 * rs * gamma[c + 1] + beta[c + 1];
    op[2] = d2 * rs * gamma[c + 2] + beta[c + 2];
    op[3] = d3 * rs * gamma[c + 3] + beta[c + 3];
}

// ---------------- launch ----------------
extern "C" void kernel_launch(void* const* d_in, const int* in_sizes, int n_in,
                              void* d_out, int out_size)
{
    const float* inputs = (const float*)d_in[0];
    const float* wq = (const float*)d_in[1];
    const float* bq = (const float*)d_in[2];
    const float* wk = (const float*)d_in[3];
    const float* bk = (const float*)d_in[4];
    const float* wv = (const float*)d_in[5];
    const float* bv = (const float*)d_in[6];
    const float* wo = (const float*)d_in[7];
    const float* bo = (const float*)d_in[8];
    const float* gamma = (const float*)d_in[9];
    const float* beta  = (const float*)d_in[10];
    float* out = (float*)d_out;

    cudaFuncSetAttribute(flash_kernel, cudaFuncAttributeMaxDynamicSharedMemorySize, FLASH_SMEM);

    dim3 gg(E_/128, M_/128);
    gemm_kernel<0><<<gg, 256>>>(inputs, wq, bq, nullptr);
    gemm_kernel<1><<<gg, 256>>>(inputs, wk, bk, nullptr);
    gemm_kernel<2><<<gg, 256>>>(inputs, wv, bv, nullptr);
    flash_kernel<<<dim3(S_/64, B_*H_), 128, FLASH_SMEM>>>();
    gemm_kernel<3><<<gg, 256>>>(nullptr, wo, bo, inputs);
    ln_kernel<<<M_, 256>>>(gamma, beta, out);
}

// round 2
// speedup vs baseline: 1.3117x; 1.3117x over previous
#include <cuda_runtime.h>
#include <cuda_bf16.h>
#include <cstdint>
#include <math_constants.h>

#define B_ 4
#define S_ 2048
#define E_ 1024
#define H_ 16
#define D_ 64
#define M_ (B_*S_)

// ---------------- scratch (static device globals; no allocation) ----------------
__device__ float g_q[(size_t)B_*H_*S_*D_];
__device__ float g_k[(size_t)B_*H_*S_*D_];
__device__ float g_v[(size_t)B_*H_*S_*D_];
__device__ float g_attn[(size_t)M_*E_];
__device__ float g_y[(size_t)M_*E_];

// ---------------- helpers ----------------
// pack two fp32 -> bf16x2 (lo = first arg, hi = second arg)
__device__ __forceinline__ unsigned pkbf(float lo, float hi){
    unsigned r; asm("cvt.rn.bf16x2.f32 %0, %1, %2;" : "=r"(r) : "f"(hi), "f"(lo)); return r;
}

__device__ __forceinline__ void mma16(float* c, const unsigned* a, const unsigned* b){
    asm volatile(
        "mma.sync.aligned.m16n8k16.row.col.f32.bf16.bf16.f32 "
        "{%0,%1,%2,%3},{%4,%5,%6,%7},{%8,%9},{%0,%1,%2,%3};"
        : "+f"(c[0]), "+f"(c[1]), "+f"(c[2]), "+f"(c[3])
        : "r"(a[0]), "r"(a[1]), "r"(a[2]), "r"(a[3]), "r"(b[0]), "r"(b[1]));
}

// ---------------- GEMM: C[M,N] = A[M,K] @ W[K,N] (+bias [+resid]) ----------------
// 128x128 block tile, BK=32, 8 warps (4x2), warp tile 32x64, bf16 mma, reg-staged
// double buffering. Smem: As[buf][m][k-pair] (20 u32/row), Bs transposed [n][k].
template<int MODE>
__global__ void __launch_bounds__(256)
gemm_kernel(const float* __restrict__ A, const float* __restrict__ W,
            const float* __restrict__ bias, const float* __restrict__ resid)
{
    __shared__ __align__(16) unsigned As[2][128][20];
    __shared__ __align__(16) unsigned Bs[2][128][20];

    const int tid = threadIdx.x, lane = tid & 31;
    const int g = lane >> 2, t4 = lane & 3;
    const int wid = tid >> 5, wm = wid & 3, wn = wid >> 2;
    const int bm = blockIdx.y * 128, bn = blockIdx.x * 128;
    const float* Ap = (MODE == 3) ? g_attn : A;

    float acc[2][8][4] = {};
    float4 ra[4], rb[4];

    #define LOAD_TILES(KT) { \
        _Pragma("unroll") for (int i = 0; i < 4; i++){ \
            int idx = tid + 256*i; \
            ra[i] = *reinterpret_cast<const float4*>(Ap + (size_t)(bm + (idx>>3))*E_ + (KT) + (idx&7)*4); \
            int kk = idx & 31, n0 = (idx>>5)*4; \
            rb[i] = *reinterpret_cast<const float4*>(W + (size_t)((KT) + kk)*E_ + bn + n0); \
        } }

    #define STORE_TILES(BUF) { \
        _Pragma("unroll") for (int i = 0; i < 4; i++){ \
            int idx = tid + 256*i; \
            uint2 pa = make_uint2(pkbf(ra[i].x, ra[i].y), pkbf(ra[i].z, ra[i].w)); \
            *reinterpret_cast<uint2*>(&As[BUF][idx>>3][(idx&7)*2]) = pa; \
            int kk = idx & 31, n0 = (idx>>5)*4; \
            __nv_bfloat16* bp = reinterpret_cast<__nv_bfloat16*>(&Bs[BUF][0][0]); \
            bp[(n0+0)*40 + kk] = __float2bfloat16(rb[i].x); \
            bp[(n0+1)*40 + kk] = __float2bfloat16(rb[i].y); \
            bp[(n0+2)*40 + kk] = __float2bfloat16(rb[i].z); \
            bp[(n0+3)*40 + kk] = __float2bfloat16(rb[i].w); \
        } }

    LOAD_TILES(0);
    STORE_TILES(0);
    __syncthreads();
    int buf = 0;

    #pragma unroll 1
    for (int kt = 0; kt < 32; kt++){
        if (kt < 31) LOAD_TILES((kt+1)*32);

        #pragma unroll
        for (int s = 0; s < 2; s++){
            unsigned af[2][4];
            #pragma unroll
            for (int mi = 0; mi < 2; mi++){
                int r = wm*32 + mi*16 + g;
                af[mi][0] = As[buf][r    ][s*8 + t4    ];
                af[mi][1] = As[buf][r + 8][s*8 + t4    ];
                af[mi][2] = As[buf][r    ][s*8 + t4 + 4];
                af[mi][3] = As[buf][r + 8][s*8 + t4 + 4];
            }
            #pragma unroll
            for (int ni = 0; ni < 8; ni++){
                int n = wn*64 + ni*8 + g;
                unsigned bf[2] = { Bs[buf][n][s*8 + t4], Bs[buf][n][s*8 + t4 + 4] };
                mma16(acc[0][ni], af[0], bf);
                mma16(acc[1][ni], af[1], bf);
            }
        }

        if (kt < 31){
            STORE_TILES(buf ^ 1);
            __syncthreads();
            buf ^= 1;
        }
    }
    #undef LOAD_TILES
    #undef STORE_TILES

    #pragma unroll
    for (int mi = 0; mi < 2; mi++)
    #pragma unroll
    for (int ni = 0; ni < 8; ni++)
    #pragma unroll
    for (int j = 0; j < 4; j++) {
        int row = bm + wm*32 + mi*16 + g + ((j & 2) ? 8 : 0);
        int col = bn + wn*64 + ni*8 + t4*2 + (j & 1);
        float v = acc[mi][ni][j] + bias[col];
        if (MODE == 3) {
            g_y[(size_t)row*E_ + col] = v + resid[(size_t)row*E_ + col];
        } else {
            int b = row >> 11, s = row & (S_ - 1), h = col >> 6, d = col & 63;
            float* op = (MODE == 0) ? g_q : (MODE == 1) ? g_k : g_v;
            op[(((size_t)(b*H_ + h))*S_ + s)*D_ + d] = v;
        }
    }
}

// ---------------- flash attention: Br=128, Bc=64, 8 warps, bf16 mma ----------------
// smem (bf16 elems, stride 72/row): Q[128][72] K[64][72] P[128][72] V[64][72] (V transposed [d][kv])
#define FQ0 0
#define FK0 9216
#define FP0 13824
#define FV0 23040
#define FSTR 72
#define FSTRU 36
#define FLASH_SMEM ((FV0 + 64*FSTR) * 2)

__global__ void __launch_bounds__(256)
flash_kernel()
{
    extern __shared__ __align__(16) char smraw[];
    __nv_bfloat16* Sb = reinterpret_cast<__nv_bfloat16*>(smraw);
    unsigned* Su = reinterpret_cast<unsigned*>(smraw);

    const int tid = threadIdx.x, lane = tid & 31, w = tid >> 5;
    const int g = lane >> 2, t4 = lane & 3;
    const int bh = blockIdx.y, q0 = blockIdx.x * 128;
    const float scale = 0.125f; // 1/sqrt(64)

    const float* qp = g_q + ((size_t)bh*S_ + q0)*D_;
    const float* kp = g_k + (size_t)bh*S_*D_;
    const float* vp = g_v + (size_t)bh*S_*D_;

    // Q fill: 128x64 fp32 -> bf16 (pre-scaled)
    #pragma unroll
    for (int i = 0; i < 8; i++) {
        int idx = tid + i*256; int r = idx >> 4, c = (idx & 15) * 4;
        float4 v = *reinterpret_cast<const float4*>(qp + (size_t)r*D_ + c);
        uint2 p = make_uint2(pkbf(v.x*scale, v.y*scale), pkbf(v.z*scale, v.w*scale));
        *reinterpret_cast<uint2*>(&Sb[FQ0 + r*FSTR + c]) = p;
    }
    __syncthreads();

    // hoist Q fragments for the whole KV loop (rows w*16..w*16+15)
    const int r0 = w*16 + g;
    unsigned qf[4][4];
    #pragma unroll
    for (int s = 0; s < 4; s++) {
        qf[s][0] = Su[(FQ0>>1) + (r0    )*FSTRU + s*8 + t4    ];
        qf[s][1] = Su[(FQ0>>1) + (r0 + 8)*FSTRU + s*8 + t4    ];
        qf[s][2] = Su[(FQ0>>1) + (r0    )*FSTRU + s*8 + t4 + 4];
        qf[s][3] = Su[(FQ0>>1) + (r0 + 8)*FSTRU + s*8 + t4 + 4];
    }

    float acc_o[8][4] = {};
    float m0 = -CUDART_INF_F, m1 = -CUDART_INF_F, l0 = 0.f, l1 = 0.f;

    for (int kv = 0; kv < S_; kv += 64) {
        __syncthreads();  // previous iteration done with Ksh/Vsh
        // K fill: [kv..kv+64) x 64, row-major
        #pragma unroll
        for (int i = 0; i < 4; i++) {
            int idx = tid + i*256; int r = idx >> 4, c = (idx & 15) * 4;
            float4 v = *reinterpret_cast<const float4*>(kp + (size_t)(kv + r)*D_ + c);
            uint2 p = make_uint2(pkbf(v.x, v.y), pkbf(v.z, v.w));
            *reinterpret_cast<uint2*>(&Sb[FK0 + r*FSTR + c]) = p;
        }
        // V fill transposed: Vsh[d][kvr]; kv-major lanes keep STS conflict-free
        #pragma unroll
        for (int i = 0; i < 4; i++) {
            int idx = tid + i*256; int kvr = idx & 63, dq = idx >> 6;
            float4 v = *reinterpret_cast<const float4*>(vp + (size_t)(kv + kvr)*D_ + dq*4);
            Sb[FV0 + (dq*4+0)*FSTR + kvr] = __float2bfloat16(v.x);
            Sb[FV0 + (dq*4+1)*FSTR + kvr] = __float2bfloat16(v.y);
            Sb[FV0 + (dq*4+2)*FSTR + kvr] = __float2bfloat16(v.z);
            Sb[FV0 + (dq*4+3)*FSTR + kvr] = __float2bfloat16(v.w);
        }
        __syncthreads();

        // S = Q @ K^T : warp rows [16w,16w+16) x 64 cols
        float sc[8][4] = {};
        #pragma unroll
        for (int s = 0; s < 4; s++) {
            #pragma unroll
            for (int ni = 0; ni < 8; ni++) {
                int n = ni*8 + g;
                unsigned b[2] = { Su[(FK0>>1) + n*FSTRU + s*8 + t4],
                                  Su[(FK0>>1) + n*FSTRU + s*8 + t4 + 4] };
                mma16(sc[ni], qf[s], b);
            }
        }

        // online softmax (rows r0, r0+8)
        float tm0 = -CUDART_INF_F, tm1 = -CUDART_INF_F;
        #pragma unroll
        for (int ni = 0; ni < 8; ni++) {
            tm0 = fmaxf(tm0, fmaxf(sc[ni][0], sc[ni][1]));
            tm1 = fmaxf(tm1, fmaxf(sc[ni][2], sc[ni][3]));
        }
        tm0 = fmaxf(tm0, __shfl_xor_sync(0xffffffffu, tm0, 1));
        tm0 = fmaxf(tm0, __shfl_xor_sync(0xffffffffu, tm0, 2));
        tm1 = fmaxf(tm1, __shfl_xor_sync(0xffffffffu, tm1, 1));
        tm1 = fmaxf(tm1, __shfl_xor_sync(0xffffffffu, tm1, 2));
        float mn0 = fmaxf(m0, tm0), mn1 = fmaxf(m1, tm1);
        float al0 = __expf(m0 - mn0), al1 = __expf(m1 - mn1);
        m0 = mn0; m1 = mn1;

        float ls0 = 0.f, ls1 = 0.f;
        #pragma unroll
        for (int ni = 0; ni < 8; ni++) {
            float p0 = __expf(sc[ni][0] - mn0);
            float p1 = __expf(sc[ni][1] - mn0);
            float p2 = __expf(sc[ni][2] - mn1);
            float p3 = __expf(sc[ni][3] - mn1);
            ls0 += p0 + p1; ls1 += p2 + p3;
            Su[(FP0>>1) + (r0    )*FSTRU + ni*4 + t4] = pkbf(p0, p1);
            Su[(FP0>>1) + (r0 + 8)*FSTRU + ni*4 + t4] = pkbf(p2, p3);
            acc_o[ni][0] *= al0; acc_o[ni][1] *= al0;
            acc_o[ni][2] *= al1; acc_o[ni][3] *= al1;
        }
        ls0 += __shfl_xor_sync(0xffffffffu, ls0, 1);
        ls0 += __shfl_xor_sync(0xffffffffu, ls0, 2);
        ls1 += __shfl_xor_sync(0xffffffffu, ls1, 1);
        ls1 += __shfl_xor_sync(0xffffffffu, ls1, 2);
        l0 = l0*al0 + ls0; l1 = l1*al1 + ls1;

        __syncwarp();  // P rows are warp-private

        // O += P @ V
        #pragma unroll
        for (int s = 0; s < 4; s++) {
            unsigned a[4];
            a[0] = Su[(FP0>>1) + (r0    )*FSTRU + s*8 + t4    ];
            a[1] = Su[(FP0>>1) + (r0 + 8)*FSTRU + s*8 + t4    ];
            a[2] = Su[(FP0>>1) + (r0    )*FSTRU + s*8 + t4 + 4];
            a[3] = Su[(FP0>>1) + (r0 + 8)*FSTRU + s*8 + t4 + 4];
            #pragma unroll
            for (int ni = 0; ni < 8; ni++) {
                int d = ni*8 + g;
                unsigned b[2] = { Su[(FV0>>1) + d*FSTRU + s*8 + t4],
                                  Su[(FV0>>1) + d*FSTRU + s*8 + t4 + 4] };
                mma16(acc_o[ni], a, b);
            }
        }
    }

    float inv0 = 1.f / l0, inv1 = 1.f / l1;
    int b = bh >> 4, h = bh & 15;
    #pragma unroll
    for (int ni = 0; ni < 8; ni++)
    #pragma unroll
    for (int j = 0; j < 4; j++) {
        int r = r0 + ((j & 2) ? 8 : 0);
        int d = ni*8 + t4*2 + (j & 1);
        float v = acc_o[ni][j] * ((j & 2) ? inv1 : inv0);
        g_attn[((size_t)b*S_ + (q0 + r))*E_ + h*64 + d] = v;
    }
}

// ---------------- LayerNorm over g_y rows -> d_out ----------------
__global__ void __launch_bounds__(256)
ln_kernel(const float* __restrict__ gamma, const float* __restrict__ beta,
          float* __restrict__ out)
{
    __shared__ float red[8];
    const int row = blockIdx.x, tid = threadIdx.x;
    const int lane = tid & 31, wid = tid >> 5;
    const float* y = g_y + (size_t)row*E_;

    float4 v = *reinterpret_cast<const float4*>(y + tid*4);
    float s = v.x + v.y + v.z + v.w;
    #pragma unroll
    for (int o = 16; o > 0; o >>= 1) s += __shfl_xor_sync(0xffffffffu, s, o);
    if (lane == 0) red[wid] = s;
    __syncthreads();
    float tot = red[0];
    #pragma unroll
    for (int i = 1; i < 8; i++) tot += red[i];
    float mean = tot * (1.f / 1024.f);

    float d0 = v.x - mean, d1 = v.y - mean, d2 = v.z - mean, d3 = v.w - mean;
    float s2 = d0*d0 + d1*d1 + d2*d2 + d3*d3;
    #pragma unroll
    for (int o = 16; o > 0; o >>= 1) s2 += __shfl_xor_sync(0xffffffffu, s2, o);
    __syncthreads();
    if (lane == 0) red[wid] = s2;
    __syncthreads();
    float tot2 = red[0];
    #pragma unroll
    for (int i = 1; i < 8; i++) tot2 += red[i];
    float rs = rsqrtf(tot2 * (1.f / 1024.f) + 1e-6f);

    const int c = tid * 4;
    float* op = out + (size_t)row*E_ + c;
    op[0] = d0 * rs * gamma[c + 0] + beta[c + 0];
    op[1] = d1 * rs * gamma[c + 1] + beta[c + 1];
    op[2] = d2 * rs * gamma[c + 2] + beta[c + 2];
    op[3] = d3 * rs * gamma[c + 3] + beta[c + 3];
}

// ---------------- launch ----------------
extern "C" void kernel_launch(void* const* d_in, const int* in_sizes, int n_in,
                              void* d_out, int out_size)
{
    const float* inputs = (const float*)d_in[0];
    const float* wq = (const float*)d_in[1];
    const float* bq = (const float*)d_in[2];
    const float* wk = (const float*)d_in[3];
    const float* bk = (const float*)d_in[4];
    const float* wv = (const float*)d_in[5];
    const float* bv = (const float*)d_in[6];
    const float* wo = (const float*)d_in[7];
    const float* bo = (const float*)d_in[8];
    const float* gamma = (const float*)d_in[9];
    const float* beta  = (const float*)d_in[10];
    float* out = (float*)d_out;

    cudaFuncSetAttribute(flash_kernel, cudaFuncAttributeMaxDynamicSharedMemorySize, FLASH_SMEM);

    dim3 gg(E_/128, M_/128);
    gemm_kernel<0><<<gg, 256>>>(inputs, wq, bq, nullptr);
    gemm_kernel<1><<<gg, 256>>>(inputs, wk, bk, nullptr);
    gemm_kernel<2><<<gg, 256>>>(inputs, wv, bv, nullptr);
    flash_kernel<<<dim3(S_/128, B_*H_), 256, FLASH_SMEM>>>();
    gemm_kernel<3><<<gg, 256>>>(nullptr, wo, bo, inputs);
    ln_kernel<<<M_, 256>>>(gamma, beta, out);
}

// round 3
// speedup vs baseline: 2.7575x; 2.1022x over previous
#include <cuda_runtime.h>
#include <cuda_bf16.h>
#include <cstdint>
#include <math_constants.h>

#define B_ 4
#define S_ 2048
#define E_ 1024
#define H_ 16
#define D_ 64
#define M_ (B_*S_)

// ---------------- scratch (static device globals; no allocation) ----------------
__device__ __nv_bfloat16 g_x[(size_t)M_*E_];     // inputs, bf16
__device__ __nv_bfloat16 g_wq[(size_t)E_*E_];
__device__ __nv_bfloat16 g_wk[(size_t)E_*E_];
__device__ __nv_bfloat16 g_wv[(size_t)E_*E_];
__device__ __nv_bfloat16 g_wo[(size_t)E_*E_];
__device__ __nv_bfloat16 g_q[(size_t)B_*H_*S_*D_];   // pre-scaled by 1/8
__device__ __nv_bfloat16 g_k[(size_t)B_*H_*S_*D_];
__device__ __nv_bfloat16 g_v[(size_t)B_*H_*S_*D_];
__device__ __nv_bfloat16 g_attn[(size_t)M_*E_];
__device__ float g_y[(size_t)M_*E_];

// ---------------- helpers ----------------
__device__ __forceinline__ unsigned pkbf(float lo, float hi){
    unsigned r; asm("cvt.rn.bf16x2.f32 %0, %1, %2;" : "=r"(r) : "f"(hi), "f"(lo)); return r;
}
__device__ __forceinline__ void mma16(float* c, const unsigned* a, const unsigned* b){
    asm volatile(
        "mma.sync.aligned.m16n8k16.row.col.f32.bf16.bf16.f32 "
        "{%0,%1,%2,%3},{%4,%5,%6,%7},{%8,%9},{%0,%1,%2,%3};"
        : "+f"(c[0]), "+f"(c[1]), "+f"(c[2]), "+f"(c[3])
        : "r"(a[0]), "r"(a[1]), "r"(a[2]), "r"(a[3]), "r"(b[0]), "r"(b[1]));
}
__device__ __forceinline__ unsigned sptr(const void* p){
    return (unsigned)__cvta_generic_to_shared(p);
}
__device__ __forceinline__ void ldsm4(unsigned& r0, unsigned& r1, unsigned& r2, unsigned& r3, unsigned a){
    asm volatile("ldmatrix.sync.aligned.m8n8.x4.shared.b16 {%0,%1,%2,%3}, [%4];"
        : "=r"(r0), "=r"(r1), "=r"(r2), "=r"(r3) : "r"(a));
}
__device__ __forceinline__ void ldsm4t(unsigned& r0, unsigned& r1, unsigned& r2, unsigned& r3, unsigned a){
    asm volatile("ldmatrix.sync.aligned.m8n8.x4.trans.shared.b16 {%0,%1,%2,%3}, [%4];"
        : "=r"(r0), "=r"(r1), "=r"(r2), "=r"(r3) : "r"(a));
}
__device__ __forceinline__ void cpa16(unsigned s, const void* g){
    asm volatile("cp.async.cg.shared.global [%0], [%1], 16;" :: "r"(s), "l"(g));
}
__device__ __forceinline__ void cpa_commit(){ asm volatile("cp.async.commit_group;"); }
__device__ __forceinline__ void cpa_wait0(){ asm volatile("cp.async.wait_group 0;"); }

// ---------------- fp32 -> bf16 conversion ----------------
__global__ void __launch_bounds__(256)
cvt_kernel(const float* __restrict__ src, int which, int n4)
{
    int i = blockIdx.x * blockDim.x + threadIdx.x;
    if (i >= n4) return;
    __nv_bfloat16* dst = (which == 0) ? g_x : (which == 1) ? g_wq :
                         (which == 2) ? g_wk : (which == 3) ? g_wv : g_wo;
    float4 v = reinterpret_cast<const float4*>(src)[i];
    reinterpret_cast<uint2*>(dst)[i] = make_uint2(pkbf(v.x, v.y), pkbf(v.z, v.w));
}

// ---------------- GEMM: C[M,N] = A[M,K] @ W[K,N] (+bias [+resid]) ----------------
// bf16 in, 128x128x32 tile, 8 warps (4x2), cp.async 2-stage, ldmatrix frags.
template<int MODE>
__global__ void __launch_bounds__(256)
gemm_kernel(const float* __restrict__ bias, const float* __restrict__ resid)
{
    __shared__ __align__(16) __nv_bfloat16 As[2][128][40];
    __shared__ __align__(16) __nv_bfloat16 Bs[2][32][136];

    const int tid = threadIdx.x, lane = tid & 31;
    const int g = lane >> 2, t4 = lane & 3;
    const int wid = tid >> 5, wm = wid & 3, wn = wid >> 2;
    const int bm = blockIdx.y * 128, bn = blockIdx.x * 128;

    const __nv_bfloat16* Ap = (MODE == 3) ? g_attn : g_x;
    const __nv_bfloat16* Wp = (MODE == 0) ? g_wq : (MODE == 1) ? g_wk :
                              (MODE == 2) ? g_wv : g_wo;

    float acc[2][8][4] = {};

    #define G_ISSUE(KT, BUF) { \
        _Pragma("unroll") for (int i = 0; i < 2; i++){ \
            int idx = tid + 256*i; \
            int ar = idx >> 2, ac = (idx & 3) * 8; \
            cpa16(sptr(&As[BUF][ar][ac]), Ap + (size_t)(bm + ar)*E_ + (KT) + ac); \
            int br = idx >> 4, bc = (idx & 15) * 8; \
            cpa16(sptr(&Bs[BUF][br][bc]), Wp + (size_t)((KT) + br)*E_ + bn + bc); \
        } \
        cpa_commit(); }

    G_ISSUE(0, 0);
    cpa_wait0();
    __syncthreads();

    int buf = 0;
    #pragma unroll 1
    for (int kt = 0; kt < 32; kt++){
        if (kt < 31) G_ISSUE((kt+1)*32, buf ^ 1);

        #pragma unroll
        for (int s = 0; s < 2; s++){
            unsigned af[2][4];
            #pragma unroll
            for (int mi = 0; mi < 2; mi++)
                ldsm4(af[mi][0], af[mi][1], af[mi][2], af[mi][3],
                      sptr(&As[buf][wm*32 + mi*16 + (lane & 15)][s*16 + ((lane & 16) >> 1)]));
            unsigned bfr[8][2];
            #pragma unroll
            for (int nb = 0; nb < 4; nb++)
                ldsm4t(bfr[2*nb][0], bfr[2*nb][1], bfr[2*nb+1][0], bfr[2*nb+1][1],
                       sptr(&Bs[buf][s*16 + (lane & 15)][wn*64 + nb*16 + ((lane & 16) >> 1)]));
            #pragma unroll
            for (int ni = 0; ni < 8; ni++){
                mma16(acc[0][ni], af[0], bfr[ni]);
                mma16(acc[1][ni], af[1], bfr[ni]);
            }
        }

        if (kt < 31){
            cpa_wait0();
            __syncthreads();
            buf ^= 1;
        }
    }
    #undef G_ISSUE

    const float qsc = (MODE == 0) ? 0.125f : 1.0f;
    #pragma unroll
    for (int mi = 0; mi < 2; mi++)
    #pragma unroll
    for (int ni = 0; ni < 8; ni++){
        int row = bm + wm*32 + mi*16 + g;
        int col = bn + wn*64 + ni*8 + t4*2;
        float b0 = bias[col], b1 = bias[col+1];
        if (MODE == 3){
            float2 r0 = *reinterpret_cast<const float2*>(&resid[(size_t)row*E_ + col]);
            float2 r1 = *reinterpret_cast<const float2*>(&resid[(size_t)(row+8)*E_ + col]);
            *reinterpret_cast<float2*>(&g_y[(size_t)row*E_ + col]) =
                make_float2(acc[mi][ni][0] + b0 + r0.x, acc[mi][ni][1] + b1 + r0.y);
            *reinterpret_cast<float2*>(&g_y[(size_t)(row+8)*E_ + col]) =
                make_float2(acc[mi][ni][2] + b0 + r1.x, acc[mi][ni][3] + b1 + r1.y);
        } else {
            __nv_bfloat16* op = (MODE == 0) ? g_q : (MODE == 1) ? g_k : g_v;
            int h = col >> 6, d = col & 63;
            unsigned p0 = pkbf((acc[mi][ni][0] + b0)*qsc, (acc[mi][ni][1] + b1)*qsc);
            unsigned p1 = pkbf((acc[mi][ni][2] + b0)*qsc, (acc[mi][ni][3] + b1)*qsc);
            int b = row >> 11, s0 = row & (S_-1);
            size_t base = (((size_t)(b*H_ + h))*S_);
            *reinterpret_cast<unsigned*>(&op[(base + s0    )*D_ + d]) = p0;
            *reinterpret_cast<unsigned*>(&op[(base + s0 + 8)*D_ + d]) = p1;
        }
    }
}

// ---------------- flash attention: Br=128, Bc=64, 8 warps, bf16, cp.async 2-stage --------
#define FQ0 0
#define FK0 9216
#define FV0 18432
#define FP0 27648
#define FSTR 72
#define FLASH_SMEM ((FP0 + 128*FSTR) * 2)

__global__ void __launch_bounds__(256)
flash_kernel()
{
    extern __shared__ __align__(16) __nv_bfloat16 fs[];
    unsigned* Su = reinterpret_cast<unsigned*>(fs);

    const int tid = threadIdx.x, lane = tid & 31, w = tid >> 5;
    const int g = lane >> 2, t4 = lane & 3;
    const int bh = blockIdx.y, q0 = blockIdx.x * 128;

    const __nv_bfloat16* qp = g_q + ((size_t)bh*S_ + q0)*D_;
    const __nv_bfloat16* kp = g_k + (size_t)bh*S_*D_;
    const __nv_bfloat16* vp = g_v + (size_t)bh*S_*D_;

    #define KV_ISSUE(KV, BUF) { \
        _Pragma("unroll") for (int i = 0; i < 2; i++){ \
            int idx = tid + 256*i; int r = idx >> 3, c = (idx & 7) * 8; \
            cpa16(sptr(&fs[FK0 + (BUF)*4608 + r*FSTR + c]), kp + (size_t)((KV) + r)*D_ + c); \
            cpa16(sptr(&fs[FV0 + (BUF)*4608 + r*FSTR + c]), vp + (size_t)((KV) + r)*D_ + c); \
        } \
        cpa_commit(); }

    // prologue: Q (128x64) + KV tile 0 in one group
    #pragma unroll
    for (int i = 0; i < 4; i++){
        int idx = tid + 256*i; int r = idx >> 3, c = (idx & 7) * 8;
        cpa16(sptr(&fs[FQ0 + r*FSTR + c]), qp + (size_t)r*D_ + c);
    }
    KV_ISSUE(0, 0);
    cpa_wait0();
    __syncthreads();

    // hoist Q fragments for the whole KV loop (rows w*16..w*16+15)
    const int r0 = w*16 + g;
    unsigned qf[4][4];
    #pragma unroll
    for (int s = 0; s < 4; s++)
        ldsm4(qf[s][0], qf[s][1], qf[s][2], qf[s][3],
              sptr(&fs[FQ0 + (w*16 + (lane & 15))*FSTR + s*16 + ((lane & 16) >> 1)]));

    float acc_o[8][4] = {};
    float m0 = -CUDART_INF_F, m1 = -CUDART_INF_F, l0 = 0.f, l1 = 0.f;
    int buf = 0;

    #pragma unroll 1
    for (int t = 0; t < S_/64; t++){
        if (t < S_/64 - 1) KV_ISSUE((t+1)*64, buf ^ 1);

        // S = Q @ K^T : warp rows [16w,16w+16) x 64 kv cols
        float sc[8][4] = {};
        #pragma unroll
        for (int s = 0; s < 4; s++){
            unsigned bfr[8][2];
            #pragma unroll
            for (int nb = 0; nb < 4; nb++){
                int row = nb*16 + ((lane & 16) >> 1) + (lane & 7);
                int col = s*16 + (lane & 8);
                ldsm4(bfr[2*nb][0], bfr[2*nb][1], bfr[2*nb+1][0], bfr[2*nb+1][1],
                      sptr(&fs[FK0 + buf*4608 + row*FSTR + col]));
            }
            #pragma unroll
            for (int ni = 0; ni < 8; ni++) mma16(sc[ni], qf[s], bfr[ni]);
        }

        // online softmax (rows r0, r0+8)
        float tm0 = -CUDART_INF_F, tm1 = -CUDART_INF_F;
        #pragma unroll
        for (int ni = 0; ni < 8; ni++){
            tm0 = fmaxf(tm0, fmaxf(sc[ni][0], sc[ni][1]));
            tm1 = fmaxf(tm1, fmaxf(sc[ni][2], sc[ni][3]));
        }
        tm0 = fmaxf(tm0, __shfl_xor_sync(0xffffffffu, tm0, 1));
        tm0 = fmaxf(tm0, __shfl_xor_sync(0xffffffffu, tm0, 2));
        tm1 = fmaxf(tm1, __shfl_xor_sync(0xffffffffu, tm1, 1));
        tm1 = fmaxf(tm1, __shfl_xor_sync(0xffffffffu, tm1, 2));
        float mn0 = fmaxf(m0, tm0), mn1 = fmaxf(m1, tm1);
        float al0 = __expf(m0 - mn0), al1 = __expf(m1 - mn1);
        m0 = mn0; m1 = mn1;

        float ls0 = 0.f, ls1 = 0.f;
        #pragma unroll
        for (int ni = 0; ni < 8; ni++){
            float p0 = __expf(sc[ni][0] - mn0);
            float p1 = __expf(sc[ni][1] - mn0);
            float p2 = __expf(sc[ni][2] - mn1);
            float p3 = __expf(sc[ni][3] - mn1);
            ls0 += p0 + p1; ls1 += p2 + p3;
            Su[(FP0>>1) + (r0    )*(FSTR>>1) + ni*4 + t4] = pkbf(p0, p1);
            Su[(FP0>>1) + (r0 + 8)*(FSTR>>1) + ni*4 + t4] = pkbf(p2, p3);
            acc_o[ni][0] *= al0; acc_o[ni][1] *= al0;
            acc_o[ni][2] *= al1; acc_o[ni][3] *= al1;
        }
        ls0 += __shfl_xor_sync(0xffffffffu, ls0, 1);
        ls0 += __shfl_xor_sync(0xffffffffu, ls0, 2);
        ls1 += __shfl_xor_sync(0xffffffffu, ls1, 1);
        ls1 += __shfl_xor_sync(0xffffffffu, ls1, 2);
        l0 = l0*al0 + ls0; l1 = l1*al1 + ls1;

        __syncwarp();  // P rows [16w,16w+16) are warp-private

        // O += P @ V  (V stored [kv][d]; trans ldmatrix gives n=d, k=kv frags)
        #pragma unroll
        for (int s = 0; s < 4; s++){
            unsigned a[4];
            ldsm4(a[0], a[1], a[2], a[3],
                  sptr(&fs[FP0 + (w*16 + (lane & 15))*FSTR + s*16 + ((lane & 16) >> 1)]));
            unsigned bfr[8][2];
            #pragma unroll
            for (int nb = 0; nb < 4; nb++){
                int kr = s*16 + (lane & 15);
                int nc = nb*16 + ((lane & 16) >> 1);
                ldsm4t(bfr[2*nb][0], bfr[2*nb][1], bfr[2*nb+1][0], bfr[2*nb+1][1],
                       sptr(&fs[FV0 + buf*4608 + kr*FSTR + nc]));
            }
            #pragma unroll
            for (int ni = 0; ni < 8; ni++) mma16(acc_o[ni], a, bfr[ni]);
        }

        if (t < S_/64 - 1){
            cpa_wait0();
            __syncthreads();
            buf ^= 1;
        }
    }
    #undef KV_ISSUE

    float inv0 = 1.f / l0, inv1 = 1.f / l1;
    int b = bh >> 4, h = bh & 15;
    #pragma unroll
    for (int ni = 0; ni < 8; ni++){
        int d = ni*8 + t4*2;
        unsigned p0 = pkbf(acc_o[ni][0]*inv0, acc_o[ni][1]*inv0);
        unsigned p1 = pkbf(acc_o[ni][2]*inv1, acc_o[ni][3]*inv1);
        *reinterpret_cast<unsigned*>(&g_attn[((size_t)b*S_ + (q0 + r0    ))*E_ + h*64 + d]) = p0;
        *reinterpret_cast<unsigned*>(&g_attn[((size_t)b*S_ + (q0 + r0 + 8))*E_ + h*64 + d]) = p1;
    }
}

// ---------------- LayerNorm over g_y rows -> d_out ----------------
__global__ void __launch_bounds__(256)
ln_kernel(const float* __restrict__ gamma, const float* __restrict__ beta,
          float* __restrict__ out)
{
    __shared__ float red[8];
    const int row = blockIdx.x, tid = threadIdx.x;
    const int lane = tid & 31, wid = tid >> 5;
    const float* y = g_y + (size_t)row*E_;

    float4 v = *reinterpret_cast<const float4*>(y + tid*4);
    float s = v.x + v.y + v.z + v.w;
    #pragma unroll
    for (int o = 16; o > 0; o >>= 1) s += __shfl_xor_sync(0xffffffffu, s, o);
    if (lane == 0) red[wid] = s;
    __syncthreads();
    float tot = red[0];
    #pragma unroll
    for (int i = 1; i < 8; i++) tot += red[i];
    float mean = tot * (1.f / 1024.f);

    float d0 = v.x - mean, d1 = v.y - mean, d2 = v.z - mean, d3 = v.w - mean;
    float s2 = d0*d0 + d1*d1 + d2*d2 + d3*d3;
    #pragma unroll
    for (int o = 16; o > 0; o >>= 1) s2 += __shfl_xor_sync(0xffffffffu, s2, o);
    __syncthreads();
    if (lane == 0) red[wid] = s2;
    __syncthreads();
    float tot2 = red[0];
    #pragma unroll
    for (int i = 1; i < 8; i++) tot2 += red[i];
    float rs = rsqrtf(tot2 * (1.f / 1024.f) + 1e-6f);

    const int c = tid * 4;
    float* op = out + (size_t)row*E_ + c;
    op[0] = d0 * rs * gamma[c + 0] + beta[c + 0];
    op[1] = d1 * rs * gamma[c + 1] + beta[c + 1];
    op[2] = d2 * rs * gamma[c + 2] + beta[c + 2];
    op[3] = d3 * rs * gamma[c + 3] + beta[c + 3];
}

// ---------------- launch ----------------
extern "C" void kernel_launch(void* const* d_in, const int* in_sizes, int n_in,
                              void* d_out, int out_size)
{
    const float* inputs = (const float*)d_in[0];
    const float* wq = (const float*)d_in[1];
    const float* bq = (const float*)d_in[2];
    const float* wk = (const float*)d_in[3];
    const float* bk = (const float*)d_in[4];
    const float* wv = (const float*)d_in[5];
    const float* bv = (const float*)d_in[6];
    const float* wo = (const float*)d_in[7];
    const float* bo = (const float*)d_in[8];
    const float* gamma = (const float*)d_in[9];
    const float* beta  = (const float*)d_in[10];
    float* out = (float*)d_out;

    cudaFuncSetAttribute(flash_kernel, cudaFuncAttributeMaxDynamicSharedMemorySize, FLASH_SMEM);

    const int nx4 = (M_*E_)/4, nw4 = (E_*E_)/4;
    cvt_kernel<<<(nx4 + 255)/256, 256>>>(inputs, 0, nx4);
    cvt_kernel<<<(nw4 + 255)/256, 256>>>(wq, 1, nw4);
    cvt_kernel<<<(nw4 + 255)/256, 256>>>(wk, 2, nw4);
    cvt_kernel<<<(nw4 + 255)/256, 256>>>(wv, 3, nw4);
    cvt_kernel<<<(nw4 + 255)/256, 256>>>(wo, 4, nw4);

    dim3 gg(E_/128, M_/128);
    gemm_kernel<0><<<gg, 256>>>(bq, nullptr);
    gemm_kernel<1><<<gg, 256>>>(bk, nullptr);
    gemm_kernel<2><<<gg, 256>>>(bv, nullptr);
    flash_kernel<<<dim3(S_/128, B_*H_), 256, FLASH_SMEM>>>();
    gemm_kernel<3><<<gg, 256>>>(bo, inputs);
    ln_kernel<<<M_, 256>>>(gamma, beta, out);
}

// round 4
// speedup vs baseline: 2.9808x; 1.0810x over previous
#include <cuda_runtime.h>
#include <cuda_bf16.h>
#include <cstdint>
#include <math_constants.h>

#define B_ 4
#define S_ 2048
#define E_ 1024
#define H_ 16
#define D_ 64
#define M_ (B_*S_)

// ---------------- scratch (static device globals; no allocation) ----------------
__device__ __nv_bfloat16 g_x[(size_t)M_*E_];
__device__ __nv_bfloat16 g_wq[(size_t)E_*E_];
__device__ __nv_bfloat16 g_wk[(size_t)E_*E_];
__device__ __nv_bfloat16 g_wv[(size_t)E_*E_];
__device__ __nv_bfloat16 g_wo[(size_t)E_*E_];
__device__ __nv_bfloat16 g_q[(size_t)B_*H_*S_*D_];   // pre-scaled by 1/8
__device__ __nv_bfloat16 g_k[(size_t)B_*H_*S_*D_];
__device__ __nv_bfloat16 g_v[(size_t)B_*H_*S_*D_];
__device__ __nv_bfloat16 g_attn[(size_t)M_*E_];
__device__ float g_y[(size_t)M_*E_];

// ---------------- helpers ----------------
__device__ __forceinline__ unsigned pkbf(float lo, float hi){
    unsigned r; asm("cvt.rn.bf16x2.f32 %0, %1, %2;" : "=r"(r) : "f"(hi), "f"(lo)); return r;
}
__device__ __forceinline__ void mma16(float* c, const unsigned* a, const unsigned* b){
    asm volatile(
        "mma.sync.aligned.m16n8k16.row.col.f32.bf16.bf16.f32 "
        "{%0,%1,%2,%3},{%4,%5,%6,%7},{%8,%9},{%0,%1,%2,%3};"
        : "+f"(c[0]), "+f"(c[1]), "+f"(c[2]), "+f"(c[3])
        : "r"(a[0]), "r"(a[1]), "r"(a[2]), "r"(a[3]), "r"(b[0]), "r"(b[1]));
}
__device__ __forceinline__ unsigned sptr(const void* p){
    return (unsigned)__cvta_generic_to_shared(p);
}
__device__ __forceinline__ void ldsm4(unsigned& r0, unsigned& r1, unsigned& r2, unsigned& r3, unsigned a){
    asm volatile("ldmatrix.sync.aligned.m8n8.x4.shared.b16 {%0,%1,%2,%3}, [%4];"
        : "=r"(r0), "=r"(r1), "=r"(r2), "=r"(r3) : "r"(a));
}
__device__ __forceinline__ void ldsm4t(unsigned& r0, unsigned& r1, unsigned& r2, unsigned& r3, unsigned a){
    asm volatile("ldmatrix.sync.aligned.m8n8.x4.trans.shared.b16 {%0,%1,%2,%3}, [%4];"
        : "=r"(r0), "=r"(r1), "=r"(r2), "=r"(r3) : "r"(a));
}
__device__ __forceinline__ void cpa16(unsigned s, const void* g){
    asm volatile("cp.async.cg.shared.global [%0], [%1], 16;" :: "r"(s), "l"(g));
}
__device__ __forceinline__ void cpa_commit(){ asm volatile("cp.async.commit_group;"); }
template<int N> __device__ __forceinline__ void cpa_wait(){
    asm volatile("cp.async.wait_group %0;" :: "n"(N));
}

// ---------------- fused fp32 -> bf16 conversion (inputs + 4 weights) ----------------
#define NX4 ((M_*E_)/4)
#define NW4 ((E_*E_)/4)
__global__ void __launch_bounds__(256)
cvt_kernel(const float* __restrict__ x,  const float* __restrict__ wq,
           const float* __restrict__ wk, const float* __restrict__ wv,
           const float* __restrict__ wo)
{
    int i = blockIdx.x * blockDim.x + threadIdx.x;
    const float* src; __nv_bfloat16* dst; int off;
    if (i < NX4) { src = x; dst = g_x; off = i; }
    else {
        int j = i - NX4; int w = j / NW4; off = j - w*NW4;
        src = (w == 0) ? wq : (w == 1) ? wk : (w == 2) ? wv : wo;
        dst = (w == 0) ? g_wq : (w == 1) ? g_wk : (w == 2) ? g_wv : g_wo;
    }
    float4 v = reinterpret_cast<const float4*>(src)[off];
    reinterpret_cast<uint2*>(dst)[off] = make_uint2(pkbf(v.x, v.y), pkbf(v.z, v.w));
}

// ---------------- GEMM core: 128x128x32 tile, 8 warps, 4-stage cp.async ----------------
#define GSTAGES 4
#define AS_ELEM 5120   // 128*40
#define BS_ELEM 4352   // 32*136
#define GEMM_SMEM ((GSTAGES*(AS_ELEM + BS_ELEM)) * 2)
#define ASO(st) ((st)*AS_ELEM)
#define BSO(st) (GSTAGES*AS_ELEM + (st)*BS_ELEM)

// MODE 0: fused QKV (grid.x = 24: [qkv sel][8 col blocks]); MODE 3: O-proj
template<int MODE>
__global__ void __launch_bounds__(256)
gemm_kernel(const float* __restrict__ b0p, const float* __restrict__ b1p,
            const float* __restrict__ b2p, const float* __restrict__ resid)
{
    extern __shared__ __align__(16) __nv_bfloat16 sm[];

    const int tid = threadIdx.x, lane = tid & 31;
    const int g = lane >> 2, t4 = lane & 3;
    const int wid = tid >> 5, wm = wid & 3, wn = wid >> 2;
    const int sel = (MODE == 0) ? (blockIdx.x >> 3) : 0;
    const int bm = blockIdx.y * 128, bn = (MODE == 0) ? (blockIdx.x & 7) * 128 : blockIdx.x * 128;

    const __nv_bfloat16* Ap = (MODE == 3) ? g_attn : g_x;
    const __nv_bfloat16* Wp = (MODE == 3) ? g_wo :
                              (sel == 0) ? g_wq : (sel == 1) ? g_wk : g_wv;
    const float* bias = (MODE == 3) ? b0p : (sel == 0) ? b0p : (sel == 1) ? b1p : b2p;

    float acc[2][8][4] = {};

    #define G_ISSUE(KT, ST) { \
        _Pragma("unroll") for (int i = 0; i < 2; i++){ \
            int idx = tid + 256*i; \
            int ar = idx >> 2, ac = (idx & 3) * 8; \
            cpa16(sptr(&sm[ASO(ST) + ar*40 + ac]), Ap + (size_t)(bm + ar)*E_ + (KT) + ac); \
            int br = idx >> 4, bc = (idx & 15) * 8; \
            cpa16(sptr(&sm[BSO(ST) + br*136 + bc]), Wp + (size_t)((KT) + br)*E_ + bn + bc); \
        } }

    G_ISSUE(0, 0);  cpa_commit();
    G_ISSUE(32, 1); cpa_commit();
    G_ISSUE(64, 2); cpa_commit();

    #pragma unroll 1
    for (int kt = 0; kt < 32; kt++){
        cpa_wait<2>();
        __syncthreads();
        if (kt + 3 < 32) G_ISSUE((kt+3)*32, (kt+3) & 3);
        cpa_commit();

        const int st = kt & 3;
        #pragma unroll
        for (int s = 0; s < 2; s++){
            unsigned af[2][4];
            #pragma unroll
            for (int mi = 0; mi < 2; mi++)
                ldsm4(af[mi][0], af[mi][1], af[mi][2], af[mi][3],
                      sptr(&sm[ASO(st) + (wm*32 + mi*16 + (lane & 15))*40 + s*16 + ((lane & 16) >> 1)]));
            unsigned bfr[8][2];
            #pragma unroll
            for (int nb = 0; nb < 4; nb++)
                ldsm4t(bfr[2*nb][0], bfr[2*nb][1], bfr[2*nb+1][0], bfr[2*nb+1][1],
                       sptr(&sm[BSO(st) + (s*16 + (lane & 15))*136 + wn*64 + nb*16 + ((lane & 16) >> 1)]));
            #pragma unroll
            for (int ni = 0; ni < 8; ni++){
                mma16(acc[0][ni], af[0], bfr[ni]);
                mma16(acc[1][ni], af[1], bfr[ni]);
            }
        }
    }
    #undef G_ISSUE

    const float qsc = (MODE == 0 && sel == 0) ? 0.125f : 1.0f;
    #pragma unroll
    for (int mi = 0; mi < 2; mi++)
    #pragma unroll
    for (int ni = 0; ni < 8; ni++){
        int row = bm + wm*32 + mi*16 + g;
        int col = bn + wn*64 + ni*8 + t4*2;
        float b0 = bias[col], b1 = bias[col+1];
        if (MODE == 3){
            float2 r0 = *reinterpret_cast<const float2*>(&resid[(size_t)row*E_ + col]);
            float2 r1 = *reinterpret_cast<const float2*>(&resid[(size_t)(row+8)*E_ + col]);
            *reinterpret_cast<float2*>(&g_y[(size_t)row*E_ + col]) =
                make_float2(acc[mi][ni][0] + b0 + r0.x, acc[mi][ni][1] + b1 + r0.y);
            *reinterpret_cast<float2*>(&g_y[(size_t)(row+8)*E_ + col]) =
                make_float2(acc[mi][ni][2] + b0 + r1.x, acc[mi][ni][3] + b1 + r1.y);
        } else {
            __nv_bfloat16* op = (sel == 0) ? g_q : (sel == 1) ? g_k : g_v;
            int h = col >> 6, d = col & 63;
            unsigned p0 = pkbf((acc[mi][ni][0] + b0)*qsc, (acc[mi][ni][1] + b1)*qsc);
            unsigned p1 = pkbf((acc[mi][ni][2] + b0)*qsc, (acc[mi][ni][3] + b1)*qsc);
            int b = row >> 11, s0 = row & (S_-1);
            size_t base = (((size_t)(b*H_ + h))*S_);
            *reinterpret_cast<unsigned*>(&op[(base + s0    )*D_ + d]) = p0;
            *reinterpret_cast<unsigned*>(&op[(base + s0 + 8)*D_ + d]) = p1;
        }
    }
}

// ---------------- flash attention: Br=128, Bc=64, 8 warps, 3-buffer KV pipeline --------
#define FQ0 0
#define FK0 9216
#define FV0 23040
#define FP0 36864
#define FSTR 72
#define KVBUF 4608
#define FLASH_SMEM ((FP0 + 128*FSTR) * 2)

__global__ void __launch_bounds__(256)
flash_kernel()
{
    extern __shared__ __align__(16) __nv_bfloat16 fs[];
    unsigned* Su = reinterpret_cast<unsigned*>(fs);

    const int tid = threadIdx.x, lane = tid & 31, w = tid >> 5;
    const int g = lane >> 2, t4 = lane & 3;
    const int bh = blockIdx.y, q0 = blockIdx.x * 128;

    const __nv_bfloat16* qp = g_q + ((size_t)bh*S_ + q0)*D_;
    const __nv_bfloat16* kp = g_k + (size_t)bh*S_*D_;
    const __nv_bfloat16* vp = g_v + (size_t)bh*S_*D_;

    #define KV_ISSUE(KV, BUF) { \
        _Pragma("unroll") for (int i = 0; i < 2; i++){ \
            int idx = tid + 256*i; int r = idx >> 3, c = (idx & 7) * 8; \
            cpa16(sptr(&fs[FK0 + (BUF)*KVBUF + r*FSTR + c]), kp + (size_t)((KV) + r)*D_ + c); \
            cpa16(sptr(&fs[FV0 + (BUF)*KVBUF + r*FSTR + c]), vp + (size_t)((KV) + r)*D_ + c); \
        } }

    // prologue: group0 = Q + KV0, group1 = KV1
    #pragma unroll
    for (int i = 0; i < 4; i++){
        int idx = tid + 256*i; int r = idx >> 3, c = (idx & 7) * 8;
        cpa16(sptr(&fs[FQ0 + r*FSTR + c]), qp + (size_t)r*D_ + c);
    }
    KV_ISSUE(0, 0);  cpa_commit();
    KV_ISSUE(64, 1); cpa_commit();

    cpa_wait<1>();       // Q + KV0 arrived
    __syncthreads();

    const int r0 = w*16 + g;
    unsigned qf[4][4];
    #pragma unroll
    for (int s = 0; s < 4; s++)
        ldsm4(qf[s][0], qf[s][1], qf[s][2], qf[s][3],
              sptr(&fs[FQ0 + (w*16 + (lane & 15))*FSTR + s*16 + ((lane & 16) >> 1)]));

    float acc_o[8][4] = {};
    float m0 = -CUDART_INF_F, m1 = -CUDART_INF_F, l0 = 0.f, l1 = 0.f;

    #pragma unroll 1
    for (int t = 0; t < S_/64; t++){
        const int buf = t % 3;
        if (t + 2 < S_/64) KV_ISSUE((t+2)*64, (t+2) % 3);
        cpa_commit();

        // S = Q @ K^T
        float sc[8][4] = {};
        #pragma unroll
        for (int s = 0; s < 4; s++){
            unsigned bfr[8][2];
            #pragma unroll
            for (int nb = 0; nb < 4; nb++){
                int row = nb*16 + ((lane & 16) >> 1) + (lane & 7);
                int col = s*16 + (lane & 8);
                ldsm4(bfr[2*nb][0], bfr[2*nb][1], bfr[2*nb+1][0], bfr[2*nb+1][1],
                      sptr(&fs[FK0 + buf*KVBUF + row*FSTR + col]));
            }
            #pragma unroll
            for (int ni = 0; ni < 8; ni++) mma16(sc[ni], qf[s], bfr[ni]);
        }

        // online softmax (rows r0, r0+8)
        float tm0 = -CUDART_INF_F, tm1 = -CUDART_INF_F;
        #pragma unroll
        for (int ni = 0; ni < 8; ni++){
            tm0 = fmaxf(tm0, fmaxf(sc[ni][0], sc[ni][1]));
            tm1 = fmaxf(tm1, fmaxf(sc[ni][2], sc[ni][3]));
        }
        tm0 = fmaxf(tm0, __shfl_xor_sync(0xffffffffu, tm0, 1));
        tm0 = fmaxf(tm0, __shfl_xor_sync(0xffffffffu, tm0, 2));
        tm1 = fmaxf(tm1, __shfl_xor_sync(0xffffffffu, tm1, 1));
        tm1 = fmaxf(tm1, __shfl_xor_sync(0xffffffffu, tm1, 2));
        float mn0 = fmaxf(m0, tm0), mn1 = fmaxf(m1, tm1);
        float al0 = __expf(m0 - mn0), al1 = __expf(m1 - mn1);
        m0 = mn0; m1 = mn1;

        float ls0 = 0.f, ls1 = 0.f;
        #pragma unroll
        for (int ni = 0; ni < 8; ni++){
            float p0 = __expf(sc[ni][0] - mn0);
            float p1 = __expf(sc[ni][1] - mn0);
            float p2 = __expf(sc[ni][2] - mn1);
            float p3 = __expf(sc[ni][3] - mn1);
            ls0 += p0 + p1; ls1 += p2 + p3;
            Su[(FP0>>1) + (r0    )*(FSTR>>1) + ni*4 + t4] = pkbf(p0, p1);
            Su[(FP0>>1) + (r0 + 8)*(FSTR>>1) + ni*4 + t4] = pkbf(p2, p3);
            acc_o[ni][0] *= al0; acc_o[ni][1] *= al0;
            acc_o[ni][2] *= al1; acc_o[ni][3] *= al1;
        }
        ls0 += __shfl_xor_sync(0xffffffffu, ls0, 1);
        ls0 += __shfl_xor_sync(0xffffffffu, ls0, 2);
        ls1 += __shfl_xor_sync(0xffffffffu, ls1, 1);
        ls1 += __shfl_xor_sync(0xffffffffu, ls1, 2);
        l0 = l0*al0 + ls0; l1 = l1*al1 + ls1;

        __syncwarp();  // P rows [16w,16w+16) are warp-private

        // O += P @ V
        #pragma unroll
        for (int s = 0; s < 4; s++){
            unsigned a[4];
            ldsm4(a[0], a[1], a[2], a[3],
                  sptr(&fs[FP0 + (w*16 + (lane & 15))*FSTR + s*16 + ((lane & 16) >> 1)]));
            unsigned bfr[8][2];
            #pragma unroll
            for (int nb = 0; nb < 4; nb++){
                int kr = s*16 + (lane & 15);
                int nc = nb*16 + ((lane & 16) >> 1);
                ldsm4t(bfr[2*nb][0], bfr[2*nb][1], bfr[2*nb+1][0], bfr[2*nb+1][1],
                       sptr(&fs[FV0 + buf*KVBUF + kr*FSTR + nc]));
            }
            #pragma unroll
            for (int ni = 0; ni < 8; ni++) mma16(acc_o[ni], a, bfr[ni]);
        }

        if (t < S_/64 - 1){
            cpa_wait<1>();     // KV(t+1) arrived; KV(t+2) still flying
            __syncthreads();
        }
    }
    #undef KV_ISSUE

    float inv0 = 1.f / l0, inv1 = 1.f / l1;
    int b = bh >> 4, h = bh & 15;
    #pragma unroll
    for (int ni = 0; ni < 8; ni++){
        int d = ni*8 + t4*2;
        unsigned p0 = pkbf(acc_o[ni][0]*inv0, acc_o[ni][1]*inv0);
        unsigned p1 = pkbf(acc_o[ni][2]*inv1, acc_o[ni][3]*inv1);
        *reinterpret_cast<unsigned*>(&g_attn[((size_t)b*S_ + (q0 + r0    ))*E_ + h*64 + d]) = p0;
        *reinterpret_cast<unsigned*>(&g_attn[((size_t)b*S_ + (q0 + r0 + 8))*E_ + h*64 + d]) = p1;
    }
}

// ---------------- LayerNorm over g_y rows -> d_out ----------------
__global__ void __launch_bounds__(256)
ln_kernel(const float* __restrict__ gamma, const float* __restrict__ beta,
          float* __restrict__ out)
{
    __shared__ float red[8];
    const int row = blockIdx.x, tid = threadIdx.x;
    const int lane = tid & 31, wid = tid >> 5;
    const float* y = g_y + (size_t)row*E_;

    float4 v = *reinterpret_cast<const float4*>(y + tid*4);
    float s = v.x + v.y + v.z + v.w;
    #pragma unroll
    for (int o = 16; o > 0; o >>= 1) s += __shfl_xor_sync(0xffffffffu, s, o);
    if (lane == 0) red[wid] = s;
    __syncthreads();
    float tot = red[0];
    #pragma unroll
    for (int i = 1; i < 8; i++) tot += red[i];
    float mean = tot * (1.f / 1024.f);

    float d0 = v.x - mean, d1 = v.y - mean, d2 = v.z - mean, d3 = v.w - mean;
    float s2 = d0*d0 + d1*d1 + d2*d2 + d3*d3;
    #pragma unroll
    for (int o = 16; o > 0; o >>= 1) s2 += __shfl_xor_sync(0xffffffffu, s2, o);
    __syncthreads();
    if (lane == 0) red[wid] = s2;
    __syncthreads();
    float tot2 = red[0];
    #pragma unroll
    for (int i = 1; i < 8; i++) tot2 += red[i];
    float rs = rsqrtf(tot2 * (1.f / 1024.f) + 1e-6f);

    const int c = tid * 4;
    float* op = out + (size_t)row*E_ + c;
    op[0] = d0 * rs * gamma[c + 0] + beta[c + 0];
    op[1] = d1 * rs * gamma[c + 1] + beta[c + 1];
    op[2] = d2 * rs * gamma[c + 2] + beta[c + 2];
    op[3] = d3 * rs * gamma[c + 3] + beta[c + 3];
}

// ---------------- launch ----------------
extern "C" void kernel_launch(void* const* d_in, const int* in_sizes, int n_in,
                              void* d_out, int out_size)
{
    const float* inputs = (const float*)d_in[0];
    const float* wq = (const float*)d_in[1];
    const float* bq = (const float*)d_in[2];
    const float* wk = (const float*)d_in[3];
    const float* bk = (const float*)d_in[4];
    const float* wv = (const float*)d_in[5];
    const float* bv = (const float*)d_in[6];
    const float* wo = (const float*)d_in[7];
    const float* bo = (const float*)d_in[8];
    const float* gamma = (const float*)d_in[9];
    const float* beta  = (const float*)d_in[10];
    float* out = (float*)d_out;

    cudaFuncSetAttribute(flash_kernel, cudaFuncAttributeMaxDynamicSharedMemorySize, FLASH_SMEM);
    cudaFuncSetAttribute(gemm_kernel<0>, cudaFuncAttributeMaxDynamicSharedMemorySize, GEMM_SMEM);
    cudaFuncSetAttribute(gemm_kernel<3>, cudaFuncAttributeMaxDynamicSharedMemorySize, GEMM_SMEM);

    const int ncvt = NX4 + 4*NW4;
    cvt_kernel<<<(ncvt + 255)/256, 256>>>(inputs, wq, wk, wv, wo);

    gemm_kernel<0><<<dim3(24, M_/128), 256, GEMM_SMEM>>>(bq, bk, bv, nullptr);
    flash_kernel<<<dim3(S_/128, B_*H_), 256, FLASH_SMEM>>>();
    gemm_kernel<3><<<dim3(8, M_/128), 256, GEMM_SMEM>>>(bo, nullptr, nullptr, inputs);
    ln_kernel<<<M_, 256>>>(gamma, beta, out);
}

// round 6
// speedup vs baseline: 3.3956x; 1.1392x over previous
#include <cuda_runtime.h>
#include <cuda_bf16.h>
#include <cstdint>
#include <math_constants.h>

#define B_ 4
#define S_ 2048
#define E_ 1024
#define H_ 16
#define D_ 64
#define M_ (B_*S_)

// ---------------- scratch (static device globals; no allocation) ----------------
__device__ __nv_bfloat16 g_x[(size_t)M_*E_];
__device__ __nv_bfloat16 g_wq[(size_t)E_*E_];
__device__ __nv_bfloat16 g_wk[(size_t)E_*E_];
__device__ __nv_bfloat16 g_wv[(size_t)E_*E_];
__device__ __nv_bfloat16 g_wo[(size_t)E_*E_];
__device__ __nv_bfloat16 g_q[(size_t)B_*H_*S_*D_];   // pre-scaled by log2(e)/8
__device__ __nv_bfloat16 g_k[(size_t)B_*H_*S_*D_];
__device__ __nv_bfloat16 g_v[(size_t)B_*H_*S_*D_];
__device__ __nv_bfloat16 g_attn[(size_t)M_*E_];
__device__ float g_y[(size_t)M_*E_];

// ---------------- helpers ----------------
__device__ __forceinline__ unsigned pkbf(float lo, float hi){
    unsigned r; asm("cvt.rn.bf16x2.f32 %0, %1, %2;" : "=r"(r) : "f"(hi), "f"(lo)); return r;
}
__device__ __forceinline__ float ex2(float x){
    float r; asm("ex2.approx.f32 %0, %1;" : "=f"(r) : "f"(x)); return r;
}
__device__ __forceinline__ void mma16(float* c, const unsigned* a, const unsigned* b){
    asm volatile(
        "mma.sync.aligned.m16n8k16.row.col.f32.bf16.bf16.f32 "
        "{%0,%1,%2,%3},{%4,%5,%6,%7},{%8,%9},{%0,%1,%2,%3};"
        : "+f"(c[0]), "+f"(c[1]), "+f"(c[2]), "+f"(c[3])
        : "r"(a[0]), "r"(a[1]), "r"(a[2]), "r"(a[3]), "r"(b[0]), "r"(b[1]));
}
__device__ __forceinline__ unsigned sptr(const void* p){
    return (unsigned)__cvta_generic_to_shared(p);
}
__device__ __forceinline__ void ldsm4(unsigned& r0, unsigned& r1, unsigned& r2, unsigned& r3, unsigned a){
    asm volatile("ldmatrix.sync.aligned.m8n8.x4.shared.b16 {%0,%1,%2,%3}, [%4];"
        : "=r"(r0), "=r"(r1), "=r"(r2), "=r"(r3) : "r"(a));
}
__device__ __forceinline__ void ldsm4t(unsigned& r0, unsigned& r1, unsigned& r2, unsigned& r3, unsigned a){
    asm volatile("ldmatrix.sync.aligned.m8n8.x4.trans.shared.b16 {%0,%1,%2,%3}, [%4];"
        : "=r"(r0), "=r"(r1), "=r"(r2), "=r"(r3) : "r"(a));
}
__device__ __forceinline__ void cpa16(unsigned s, const void* g){
    asm volatile("cp.async.cg.shared.global [%0], [%1], 16;" :: "r"(s), "l"(g));
}
__device__ __forceinline__ void cpa_commit(){ asm volatile("cp.async.commit_group;"); }
template<int N> __device__ __forceinline__ void cpa_wait(){
    asm volatile("cp.async.wait_group %0;" :: "n"(N));
}

// ---------------- fused fp32 -> bf16 conversion (inputs + 4 weights) ----------------
#define NX4 ((M_*E_)/4)
#define NW4 ((E_*E_)/4)
__global__ void __launch_bounds__(256)
cvt_kernel(const float* __restrict__ x,  const float* __restrict__ wq,
           const float* __restrict__ wk, const float* __restrict__ wv,
           const float* __restrict__ wo)
{
    int i = blockIdx.x * blockDim.x + threadIdx.x;
    const float* src; __nv_bfloat16* dst; int off;
    if (i < NX4) { src = x; dst = g_x; off = i; }
    else {
        int j = i - NX4; int w = j / NW4; off = j - w*NW4;
        src = (w == 0) ? wq : (w == 1) ? wk : (w == 2) ? wv : wo;
        dst = (w == 0) ? g_wq : (w == 1) ? g_wk : (w == 2) ? g_wv : g_wo;
    }
    float4 v = reinterpret_cast<const float4*>(src)[off];
    reinterpret_cast<uint2*>(dst)[off] = make_uint2(pkbf(v.x, v.y), pkbf(v.z, v.w));
}

// ---------------- GEMM: 128x128x32 tile, 8 warps, 4-stage cp.async, frag pipeline ----
#define GSTAGES 4
#define AS_ELEM 5120   // 128*40
#define BS_ELEM 4352   // 32*136
#define GEMM_SMEM ((GSTAGES*(AS_ELEM + BS_ELEM)) * 2)
#define ASO(st) ((st)*AS_ELEM)
#define BSO(st) (GSTAGES*AS_ELEM + (st)*BS_ELEM)

// MODE 0: fused QKV (grid.x = 24: [qkv sel][8 col blocks]); MODE 3: O-proj
template<int MODE>
__global__ void __launch_bounds__(256, 2)
gemm_kernel(const float* __restrict__ b0p, const float* __restrict__ b1p,
            const float* __restrict__ b2p, const float* __restrict__ resid)
{
    extern __shared__ __align__(16) __nv_bfloat16 sm[];

    const int tid = threadIdx.x, lane = tid & 31;
    const int g = lane >> 2, t4 = lane & 3;
    const int wid = tid >> 5, wm = wid & 3, wn = wid >> 2;
    const int sel = (MODE == 0) ? (blockIdx.x >> 3) : 0;
    const int bm = blockIdx.y * 128, bn = (MODE == 0) ? (blockIdx.x & 7) * 128 : blockIdx.x * 128;

    const __nv_bfloat16* Ap = (MODE == 3) ? g_attn : g_x;
    const __nv_bfloat16* Wp = (MODE == 3) ? g_wo :
                              (sel == 0) ? g_wq : (sel == 1) ? g_wk : g_wv;
    const float* bias = (MODE == 3) ? b0p : (sel == 0) ? b0p : (sel == 1) ? b1p : b2p;

    float acc[2][8][4] = {};

    #define G_ISSUE(KT, ST) { \
        _Pragma("unroll") for (int i = 0; i < 2; i++){ \
            int idx = tid + 256*i; \
            int ar = idx >> 2, ac = (idx & 3) * 8; \
            cpa16(sptr(&sm[ASO(ST) + ar*40 + ac]), Ap + (size_t)(bm + ar)*E_ + (KT) + ac); \
            int br = idx >> 4, bc = (idx & 15) * 8; \
            cpa16(sptr(&sm[BSO(ST) + br*136 + bc]), Wp + (size_t)((KT) + br)*E_ + bn + bc); \
        } \
        cpa_commit(); }

    #define LDFRAG(ST, S, A, Bf) { \
        _Pragma("unroll") for (int mi = 0; mi < 2; mi++) \
            ldsm4(A[mi][0], A[mi][1], A[mi][2], A[mi][3], \
                  sptr(&sm[ASO(ST) + (wm*32 + mi*16 + (lane & 15))*40 + (S)*16 + ((lane & 16) >> 1)])); \
        _Pragma("unroll") for (int nb = 0; nb < 4; nb++) \
            ldsm4t(Bf[2*nb][0], Bf[2*nb][1], Bf[2*nb+1][0], Bf[2*nb+1][1], \
                   sptr(&sm[BSO(ST) + ((S)*16 + (lane & 15))*136 + wn*64 + nb*16 + ((lane & 16) >> 1)])); }

    #define MMA_ALL(A, Bf) { \
        _Pragma("unroll") for (int ni = 0; ni < 8; ni++){ \
            mma16(acc[0][ni], A[0], Bf[ni]); \
            mma16(acc[1][ni], A[1], Bf[ni]); } }

    G_ISSUE(0, 0);
    G_ISSUE(32, 1);
    G_ISSUE(64, 2);

    cpa_wait<2>();
    __syncthreads();

    unsigned cA[2][4], cB[8][2], nA[2][4], nB[8][2];
    LDFRAG(0, 0, cA, cB);

    #pragma unroll 1
    for (int kt = 0; kt < 32; kt++){
        const int st = kt & 3;
        if (kt + 3 < 32) G_ISSUE((kt+3)*32, (kt+3) & 3);
        LDFRAG(st, 1, nA, nB);
        MMA_ALL(cA, cB);
        if (kt + 1 < 32){
            cpa_wait<2>();
            __syncthreads();
            LDFRAG((kt+1) & 3, 0, cA, cB);
        }
        MMA_ALL(nA, nB);
    }
    #undef G_ISSUE
    #undef LDFRAG
    #undef MMA_ALL

    const float qsc = (MODE == 0 && sel == 0) ? 0.125f*1.44269504f : 1.0f;
    #pragma unroll
    for (int mi = 0; mi < 2; mi++)
    #pragma unroll
    for (int ni = 0; ni < 8; ni++){
        int row = bm + wm*32 + mi*16 + g;
        int col = bn + wn*64 + ni*8 + t4*2;
        float b0 = bias[col], b1 = bias[col+1];
        if (MODE == 3){
            float2 r0 = *reinterpret_cast<const float2*>(&resid[(size_t)row*E_ + col]);
            float2 r1 = *reinterpret_cast<const float2*>(&resid[(size_t)(row+8)*E_ + col]);
            *reinterpret_cast<float2*>(&g_y[(size_t)row*E_ + col]) =
                make_float2(acc[mi][ni][0] + b0 + r0.x, acc[mi][ni][1] + b1 + r0.y);
            *reinterpret_cast<float2*>(&g_y[(size_t)(row+8)*E_ + col]) =
                make_float2(acc[mi][ni][2] + b0 + r1.x, acc[mi][ni][3] + b1 + r1.y);
        } else {
            __nv_bfloat16* op = (sel == 0) ? g_q : (sel == 1) ? g_k : g_v;
            int h = col >> 6, d = col & 63;
            unsigned p0 = pkbf((acc[mi][ni][0] + b0)*qsc, (acc[mi][ni][1] + b1)*qsc);
            unsigned p1 = pkbf((acc[mi][ni][2] + b0)*qsc, (acc[mi][ni][3] + b1)*qsc);
            int b = row >> 11, s0 = row & (S_-1);
            size_t base = (((size_t)(b*H_ + h))*S_);
            *reinterpret_cast<unsigned*>(&op[(base + s0    )*D_ + d]) = p0;
            *reinterpret_cast<unsigned*>(&op[(base + s0 + 8)*D_ + d]) = p1;
        }
    }
}

// ---------------- flash attention: Br=128, Bc=64, 8 warps, P kept in registers --------
#define FQ0 0
#define FK0 9216
#define FV0 23040
#define FSTR 72
#define KVBUF 4608
#define FLASH_SMEM ((FV0 + 3*KVBUF) * 2)

__global__ void __launch_bounds__(256)
flash_kernel()
{
    extern __shared__ __align__(16) __nv_bfloat16 fs[];

    const int tid = threadIdx.x, lane = tid & 31, w = tid >> 5;
    const int g = lane >> 2, t4 = lane & 3;
    const int bh = blockIdx.y, q0 = blockIdx.x * 128;

    const __nv_bfloat16* qp = g_q + ((size_t)bh*S_ + q0)*D_;
    const __nv_bfloat16* kp = g_k + (size_t)bh*S_*D_;
    const __nv_bfloat16* vp = g_v + (size_t)bh*S_*D_;

    #define KV_ISSUE(KV, BUF) { \
        _Pragma("unroll") for (int i = 0; i < 2; i++){ \
            int idx = tid + 256*i; int r = idx >> 3, c = (idx & 7) * 8; \
            cpa16(sptr(&fs[FK0 + (BUF)*KVBUF + r*FSTR + c]), kp + (size_t)((KV) + r)*D_ + c); \
            cpa16(sptr(&fs[FV0 + (BUF)*KVBUF + r*FSTR + c]), vp + (size_t)((KV) + r)*D_ + c); \
        } }

    // K frags for QK (row-major K tile, n = kv row)
    #define LDK(BUF, S, KB) { \
        _Pragma("unroll") for (int nb = 0; nb < 4; nb++){ \
            int row = nb*16 + ((lane & 16) >> 1) + (lane & 7); \
            int col = (S)*16 + (lane & 8); \
            ldsm4(KB[2*nb][0], KB[2*nb][1], KB[2*nb+1][0], KB[2*nb+1][1], \
                  sptr(&fs[FK0 + (BUF)*KVBUF + row*FSTR + col])); } }

    // V frags for PV (trans: n = d, k = kv)
    #define LDV(BUF, S, VB) { \
        _Pragma("unroll") for (int nb = 0; nb < 4; nb++){ \
            int kr = (S)*16 + (lane & 15); \
            int nc = nb*16 + ((lane & 16) >> 1); \
            ldsm4t(VB[2*nb][0], VB[2*nb][1], VB[2*nb+1][0], VB[2*nb+1][1], \
                   sptr(&fs[FV0 + (BUF)*KVBUF + kr*FSTR + nc])); } }

    // prologue: group0 = Q + KV0, group1 = KV1
    #pragma unroll
    for (int i = 0; i < 4; i++){
        int idx = tid + 256*i; int r = idx >> 3, c = (idx & 7) * 8;
        cpa16(sptr(&fs[FQ0 + r*FSTR + c]), qp + (size_t)r*D_ + c);
    }
    KV_ISSUE(0, 0);  cpa_commit();
    KV_ISSUE(64, 1); cpa_commit();

    cpa_wait<1>();
    __syncthreads();

    const int r0 = w*16 + g;
    unsigned qf[4][4];
    #pragma unroll
    for (int s = 0; s < 4; s++)
        ldsm4(qf[s][0], qf[s][1], qf[s][2], qf[s][3],
              sptr(&fs[FQ0 + (w*16 + (lane & 15))*FSTR + s*16 + ((lane & 16) >> 1)]));

    float acc_o[8][4] = {};
    float m0 = -CUDART_INF_F, m1 = -CUDART_INF_F, l0 = 0.f, l1 = 0.f;

    #pragma unroll 1
    for (int t = 0; t < S_/64; t++){
        const int buf = t % 3;
        if (t + 2 < S_/64) KV_ISSUE((t+2)*64, (t+2) % 3);
        cpa_commit();

        // S = Q @ K^T (K frags double-buffered)
        float sc[8][4] = {};
        {
            unsigned kb[2][8][2];
            LDK(buf, 0, kb[0]);
            #pragma unroll
            for (int s = 0; s < 4; s++){
                if (s < 3) LDK(buf, s+1, kb[(s+1)&1]);
                #pragma unroll
                for (int ni = 0; ni < 8; ni++) mma16(sc[ni], qf[s], kb[s&1][ni]);
            }
        }

        // online softmax in log2 domain (Q pre-scaled by log2e/8)
        float tm0 = -CUDART_INF_F, tm1 = -CUDART_INF_F;
        #pragma unroll
        for (int ni = 0; ni < 8; ni++){
            tm0 = fmaxf(tm0, fmaxf(sc[ni][0], sc[ni][1]));
            tm1 = fmaxf(tm1, fmaxf(sc[ni][2], sc[ni][3]));
        }
        tm0 = fmaxf(tm0, __shfl_xor_sync(0xffffffffu, tm0, 1));
        tm0 = fmaxf(tm0, __shfl_xor_sync(0xffffffffu, tm0, 2));
        tm1 = fmaxf(tm1, __shfl_xor_sync(0xffffffffu, tm1, 1));
        tm1 = fmaxf(tm1, __shfl_xor_sync(0xffffffffu, tm1, 2));
        float mn0 = fmaxf(m0, tm0), mn1 = fmaxf(m1, tm1);
        float al0 = ex2(m0 - mn0), al1 = ex2(m1 - mn1);
        m0 = mn0; m1 = mn1;

        // exp and pack P directly into PV A-fragments (QK C-layout == PV A-layout)
        float ls0 = 0.f, ls1 = 0.f;
        unsigned pa[4][4];
        #pragma unroll
        for (int s = 0; s < 4; s++){
            float p00 = ex2(sc[2*s  ][0] - mn0), p01 = ex2(sc[2*s  ][1] - mn0);
            float p02 = ex2(sc[2*s  ][2] - mn1), p03 = ex2(sc[2*s  ][3] - mn1);
            float p10 = ex2(sc[2*s+1][0] - mn0), p11 = ex2(sc[2*s+1][1] - mn0);
            float p12 = ex2(sc[2*s+1][2] - mn1), p13 = ex2(sc[2*s+1][3] - mn1);
            ls0 += p00 + p01 + p10 + p11;
            ls1 += p02 + p03 + p12 + p13;
            pa[s][0] = pkbf(p00, p01);
            pa[s][1] = pkbf(p02, p03);
            pa[s][2] = pkbf(p10, p11);
            pa[s][3] = pkbf(p12, p13);
        }
        #pragma unroll
        for (int ni = 0; ni < 8; ni++){
            acc_o[ni][0] *= al0; acc_o[ni][1] *= al0;
            acc_o[ni][2] *= al1; acc_o[ni][3] *= al1;
        }
        ls0 += __shfl_xor_sync(0xffffffffu, ls0, 1);
        ls0 += __shfl_xor_sync(0xffffffffu, ls0, 2);
        ls1 += __shfl_xor_sync(0xffffffffu, ls1, 1);
        ls1 += __shfl_xor_sync(0xffffffffu, ls1, 2);
        l0 = l0*al0 + ls0; l1 = l1*al1 + ls1;

        // O += P @ V (V frags double-buffered)
        {
            unsigned vb[2][8][2];
            LDV(buf, 0, vb[0]);
            #pragma unroll
            for (int s = 0; s < 4; s++){
                if (s < 3) LDV(buf, s+1, vb[(s+1)&1]);
                #pragma unroll
                for (int ni = 0; ni < 8; ni++) mma16(acc_o[ni], pa[s], vb[s&1][ni]);
            }
        }

        if (t < S_/64 - 1){
            cpa_wait<1>();
            __syncthreads();
        }
    }
    #undef KV_ISSUE
    #undef LDK
    #undef LDV

    float inv0 = 1.f / l0, inv1 = 1.f / l1;
    int b = bh >> 4, h = bh & 15;
    #pragma unroll
    for (int ni = 0; ni < 8; ni++){
        int d = ni*8 + t4*2;
        unsigned p0 = pkbf(acc_o[ni][0]*inv0, acc_o[ni][1]*inv0);
        unsigned p1 = pkbf(acc_o[ni][2]*inv1, acc_o[ni][3]*inv1);
        *reinterpret_cast<unsigned*>(&g_attn[((size_t)b*S_ + (q0 + r0    ))*E_ + h*64 + d]) = p0;
        *reinterpret_cast<unsigned*>(&g_attn[((size_t)b*S_ + (q0 + r0 + 8))*E_ + h*64 + d]) = p1;
    }
}

// ---------------- LayerNorm over g_y rows -> d_out ----------------
__global__ void __launch_bounds__(256)
ln_kernel(const float* __restrict__ gamma, const float* __restrict__ beta,
          float* __restrict__ out)
{
    __shared__ float red[8];
    const int row = blockIdx.x, tid = threadIdx.x;
    const int lane = tid & 31, wid = tid >> 5;
    const float* y = g_y + (size_t)row*E_;

    float4 v = *reinterpret_cast<const float4*>(y + tid*4);
    float s = v.x + v.y + v.z + v.w;
    #pragma unroll
    for (int o = 16; o > 0; o >>= 1) s += __shfl_xor_sync(0xffffffffu, s, o);
    if (lane == 0) red[wid] = s;
    __syncthreads();
    float tot = red[0];
    #pragma unroll
    for (int i = 1; i < 8; i++) tot += red[i];
    float mean = tot * (1.f / 1024.f);

    float d0 = v.x - mean, d1 = v.y - mean, d2 = v.z - mean, d3 = v.w - mean;
    float s2 = d0*d0 + d1*d1 + d2*d2 + d3*d3;
    #pragma unroll
    for (int o = 16; o > 0; o >>= 1) s2 += __shfl_xor_sync(0xffffffffu, s2, o);
    __syncthreads();
    if (lane == 0) red[wid] = s2;
    __syncthreads();
    float tot2 = red[0];
    #pragma unroll
    for (int i = 1; i < 8; i++) tot2 += red[i];
    float rs = rsqrtf(tot2 * (1.f / 1024.f) + 1e-6f);

    const int c = tid * 4;
    float* op = out + (size_t)row*E_ + c;
    op[0] = d0 * rs * gamma[c + 0] + beta[c + 0];
    op[1] = d1 * rs * gamma[c + 1] + beta[c + 1];
    op[2] = d2 * rs * gamma[c + 2] + beta[c + 2];
    op[3] = d3 * rs * gamma[c + 3] + beta[c + 3];
}

// ---------------- launch ----------------
extern "C" void kernel_launch(void* const* d_in, const int* in_sizes, int n_in,
                              void* d_out, int out_size)
{
    const float* inputs = (const float*)d_in[0];
    const float* wq = (const float*)d_in[1];
    const float* bq = (const float*)d_in[2];
    const float* wk = (const float*)d_in[3];
    const float* bk = (const float*)d_in[4];
    const float* wv = (const float*)d_in[5];
    const float* bv = (const float*)d_in[6];
    const float* wo = (const float*)d_in[7];
    const float* bo = (const float*)d_in[8];
    const float* gamma = (const float*)d_in[9];
    const float* beta  = (const float*)d_in[10];
    float* out = (float*)d_out;

    cudaFuncSetAttribute(flash_kernel, cudaFuncAttributeMaxDynamicSharedMemorySize, FLASH_SMEM);
    cudaFuncSetAttribute(gemm_kernel<0>, cudaFuncAttributeMaxDynamicSharedMemorySize, GEMM_SMEM);
    cudaFuncSetAttribute(gemm_kernel<3>, cudaFuncAttributeMaxDynamicSharedMemorySize, GEMM_SMEM);

    const int ncvt = NX4 + 4*NW4;
    cvt_kernel<<<(ncvt + 255)/256, 256>>>(inputs, wq, wk, wv, wo);

    gemm_kernel<0><<<dim3(24, M_/128), 256, GEMM_SMEM>>>(bq, bk, bv, nullptr);
    flash_kernel<<<dim3(S_/128, B_*H_), 256, FLASH_SMEM>>>();
    gemm_kernel<3><<<dim3(8, M_/128), 256, GEMM_SMEM>>>(bo, nullptr, nullptr, inputs);
    ln_kernel<<<M_, 256>>>(gamma, beta, out);
}